// round 10
// baseline (speedup 1.0000x reference)
#include <cuda_runtime.h>
#include <cstdint>

// Problem constants
#define N_ROWS 8192
#define D_DIM  64
#define B_HALF 1024          // epsilon = [tmp; -tmp] antisymmetry folds B=2048 -> 1024
#define TWO_PI 6.283185307179586f

// Tiling
#define TBM 256              // main threads per block
#define ROWS_T 128           // rows per block
#define BT 64                // basis per block
#define NG (B_HALF / BT)     // 16 b-groups

// Shared layout (R3-proven: scalar tiles, in-register splats)
#define SX_STRIDE 132        // floats per k-row of x tile
#define SS_STRIDE 68         // floats per k-row of s tile
#define SU_STRIDE 65         // u64 per b-row of U tile (alias of x region)
#define OFF_X  0
#define OFF_S  (64 * SX_STRIDE * 4)                 // 33792
#define OFF_W  (OFF_S + 64 * SS_STRIDE * 4)         // 51200
#define SMEM_BYTES (OFF_W + 2 * BT * 4)             // 51712

typedef unsigned long long u64;

// Packed f32x2 math (Blackwell FFMA2)
#define FMA2(d, a, b, c) asm("fma.rn.f32x2 %0, %1, %2, %3;" : "=l"(d) : "l"(a), "l"(b), "l"(c))
#define PACK2(d, lo, hi) asm("mov.b64 %0, {%1, %2};"        : "=l"(d) : "f"(lo), "f"(hi))
#define UNPACK2(lo, hi, s) asm("mov.b64 {%0, %1}, %2;"      : "=f"(lo), "=f"(hi) : "l"(s))

// Vector float atomic-add, no return (REDG.128). sm_90+.
#define RED_ADD_V4(ptr, a, b, c, d) \
    asm volatile("red.global.add.v4.f32 [%0], {%1, %2, %3, %4};" \
                 :: "l"(ptr), "f"(a), "f"(b), "f"(c), "f"(d) : "memory")

// Device scratch
__device__ float g_S[B_HALF * D_DIM];     // s[b][j] = eps[b][j] / (2*pi*lam[j])
__device__ float g_M[B_HALF * D_DIM];     // mat[b][i]
__device__ float g_ws[B_HALF];            // -(w_s[b] + w_s[b+1024])
__device__ float g_wc[B_HALF];            //  (w_c[b] - w_c[b+1024])

// ---------------------------------------------------------------------------
// Precompute S, mat, effective weights; also zero the output (it accumulates
// via red.global.add in main). 256 blocks x 256 threads.
// ---------------------------------------------------------------------------
__global__ void prep_kernel(const float* __restrict__ eps,
                            const float* __restrict__ lam,
                            const float* __restrict__ eta,
                            const float* __restrict__ w,
                            float4* __restrict__ out) {
    int idx = blockIdx.x * blockDim.x + threadIdx.x;
    if (idx < B_HALF * D_DIM) {
        int b = idx >> 6;
        int j = idx & 63;
        float l = lam[j];
        g_S[idx] = eps[idx] / (TWO_PI * l);
        float eta2 = eta[0] * eta[0];
        float m;
        if (j < 32) {
            m = eps[b * 64 + 32 + j] / lam[32 + j];
        } else {
            m = -eps[b * 64 + (j - 32)] / lam[j - 32] - eta2 * eps[idx] / l;
        }
        g_M[idx] = m;
    }
    if (idx < B_HALF) {
        g_ws[idx] = -(w[idx] + w[idx + B_HALF]);
        g_wc[idx] = w[2 * B_HALF + idx] - w[3 * B_HALF + idx];
    }
    // Zero output: 131072 float4 across 65536 threads -> 2 each
    out[idx]         = make_float4(0.f, 0.f, 0.f, 0.f);
    out[idx + 65536] = make_float4(0.f, 0.f, 0.f, 0.f);
}

// ---------------------------------------------------------------------------
// Main fused kernel (R3/R9 measured-best structure). R10 change: occupancy 4
// (regs capped to 64) + deeper unroll, to lift issue% from 43.8.
// Thread (ty = tid/16, tx = tid%16):
//   Phase A: 8 rows (4 rowpairs) x 4 basis (b = 4tx..+3)
//   Phase B: 8 rows x 4 dims (d = 4tx..+3), K = 64 basis of this group
// ---------------------------------------------------------------------------
__global__ void __launch_bounds__(TBM, 4)
main_kernel(const float* __restrict__ x, float* __restrict__ out) {
    extern __shared__ char smem[];
    float* sXf = (float*)(smem + OFF_X);   // [64 k][SX_STRIDE]  x transposed
    float* sSf = (float*)(smem + OFF_S);   // [64 k][SS_STRIDE]  s transposed
    float* sW  = (float*)(smem + OFF_W);   // [2*BT] interleaved ws/wc
    u64*   sUu = (u64*)(smem + OFF_X);     // alias: [64 b][SU_STRIDE] U rowpairs
    float* sMf = (float*)(smem + OFF_S);   // alias: [64 b][64] M tile

    const int tid = threadIdx.x;
    const int ty  = tid >> 4;              // 0..15
    const int tx  = tid & 15;              // 0..15
    const int bx  = blockIdx.x;
    const int g   = blockIdx.y;
    const int b0  = g * BT;

    // ---- Stage x/s tiles transposed into shared memory ----
    {
        const float4* xg = (const float4*)(x + (size_t)bx * ROWS_T * D_DIM);
        #pragma unroll
        for (int it = 0; it < 8; ++it) {
            int i  = tid + it * TBM;       // float4 id, 2048 total
            int r  = i >> 4;
            int k4 = (i & 15) * 4;
            float4 v = xg[i];
            sXf[(k4 + 0) * SX_STRIDE + r] = v.x;
            sXf[(k4 + 1) * SX_STRIDE + r] = v.y;
            sXf[(k4 + 2) * SX_STRIDE + r] = v.z;
            sXf[(k4 + 3) * SX_STRIDE + r] = v.w;
        }
        const float4* sg = (const float4*)(g_S + (size_t)b0 * D_DIM);
        #pragma unroll
        for (int it = 0; it < 4; ++it) {
            int i  = tid + it * TBM;       // float4 id, 1024 total
            int b  = i >> 4;
            int k4 = (i & 15) * 4;
            float4 v = sg[i];
            sSf[(k4 + 0) * SS_STRIDE + b] = v.x;
            sSf[(k4 + 1) * SS_STRIDE + b] = v.y;
            sSf[(k4 + 2) * SS_STRIDE + b] = v.z;
            sSf[(k4 + 3) * SS_STRIDE + b] = v.w;
        }
        if (tid < BT) {
            sW[2 * tid]     = g_ws[b0 + tid];
            sW[2 * tid + 1] = g_wc[b0 + tid];
        }
    }
    __syncthreads();

    // ---- Phase A: sim tile, rows packed 2/u64. acc[i=b_local][j=rowpair] ----
    u64 acc[4][4];
    #pragma unroll
    for (int i = 0; i < 4; ++i)
        #pragma unroll
        for (int j = 0; j < 4; ++j) acc[i][j] = 0ull;

    {
        const float* xbase = sXf + 8 * ty;       // rows 8*ty .. 8*ty+7
        const float* sbase = sSf + 4 * tx;       // basis 4*tx .. +3
        #pragma unroll 4
        for (int k = 0; k < 64; ++k) {
            const float4* xr = (const float4*)(xbase + k * SX_STRIDE);
            float4 xa = xr[0];
            float4 xb = xr[1];
            u64 xv0, xv1, xv2, xv3;
            PACK2(xv0, xa.x, xa.y);
            PACK2(xv1, xa.z, xa.w);
            PACK2(xv2, xb.x, xb.y);
            PACK2(xv3, xb.z, xb.w);
            float4 sv = *(const float4*)(sbase + k * SS_STRIDE);
            u64 s0, s1, s2, s3;
            PACK2(s0, sv.x, sv.x);
            PACK2(s1, sv.y, sv.y);
            PACK2(s2, sv.z, sv.z);
            PACK2(s3, sv.w, sv.w);
            FMA2(acc[0][0], xv0, s0, acc[0][0]);
            FMA2(acc[0][1], xv1, s0, acc[0][1]);
            FMA2(acc[0][2], xv2, s0, acc[0][2]);
            FMA2(acc[0][3], xv3, s0, acc[0][3]);
            FMA2(acc[1][0], xv0, s1, acc[1][0]);
            FMA2(acc[1][1], xv1, s1, acc[1][1]);
            FMA2(acc[1][2], xv2, s1, acc[1][2]);
            FMA2(acc[1][3], xv3, s1, acc[1][3]);
            FMA2(acc[2][0], xv0, s2, acc[2][0]);
            FMA2(acc[2][1], xv1, s2, acc[2][1]);
            FMA2(acc[2][2], xv2, s2, acc[2][2]);
            FMA2(acc[2][3], xv3, s2, acc[2][3]);
            FMA2(acc[3][0], xv0, s3, acc[3][0]);
            FMA2(acc[3][1], xv1, s3, acc[3][1]);
            FMA2(acc[3][2], xv2, s3, acc[3][2]);
            FMA2(acc[3][3], xv3, s3, acc[3][3]);
        }
    }

    // ---- Epilogue: acc (sim/2pi) -> u = sin*ws + cos*wc ----
    #pragma unroll
    for (int i = 0; i < 4; ++i) {
        int bl = tx * 4 + i;
        float ws = sW[2 * bl];
        float wc = sW[2 * bl + 1];
        #pragma unroll
        for (int j = 0; j < 4; ++j) {
            float p0, p1;
            UNPACK2(p0, p1, acc[i][j]);
            float r0 = p0 - rintf(p0);
            float r1 = p1 - rintf(p1);
            float t0 = r0 * TWO_PI;
            float t1 = r1 * TWO_PI;
            float u0 = __sinf(t0) * ws + __cosf(t0) * wc;
            float u1 = __sinf(t1) * ws + __cosf(t1) * wc;
            PACK2(acc[i][j], u0, u1);
        }
    }

    __syncthreads();   // all shared reads of sXf/sSf done before aliasing

    // ---- Write U tile (rowpair-packed) + stage M tile into aliased smem ----
    #pragma unroll
    for (int i = 0; i < 4; ++i) {
        int bl = tx * 4 + i;
        #pragma unroll
        for (int j = 0; j < 4; ++j) {
            sUu[bl * SU_STRIDE + ty * 4 + j] = acc[i][j];
        }
    }
    {
        const float4* mg = (const float4*)(g_M + (size_t)b0 * D_DIM);
        float4* md = (float4*)sMf;
        #pragma unroll
        for (int it = 0; it < 4; ++it) {
            int i = tid + it * TBM;
            md[i] = mg[i];
        }
    }
    __syncthreads();

    // ---- Phase B: f_partial = U @ M.  o[j=rowpair][i=d_local] ----
    u64 o[4][4];
    #pragma unroll
    for (int j = 0; j < 4; ++j)
        #pragma unroll
        for (int i = 0; i < 4; ++i) o[j][i] = 0ull;

    {
        const u64*   ubase = sUu + 4 * ty;
        const float* mbase = sMf + 4 * tx;
        #pragma unroll 4
        for (int b = 0; b < 64; ++b) {
            u64 uv0 = ubase[b * SU_STRIDE + 0];
            u64 uv1 = ubase[b * SU_STRIDE + 1];
            u64 uv2 = ubase[b * SU_STRIDE + 2];
            u64 uv3 = ubase[b * SU_STRIDE + 3];
            float4 mv = *(const float4*)(mbase + b * 64);
            u64 m0, m1, m2, m3;
            PACK2(m0, mv.x, mv.x);
            PACK2(m1, mv.y, mv.y);
            PACK2(m2, mv.z, mv.z);
            PACK2(m3, mv.w, mv.w);
            FMA2(o[0][0], uv0, m0, o[0][0]);
            FMA2(o[0][1], uv0, m1, o[0][1]);
            FMA2(o[0][2], uv0, m2, o[0][2]);
            FMA2(o[0][3], uv0, m3, o[0][3]);
            FMA2(o[1][0], uv1, m0, o[1][0]);
            FMA2(o[1][1], uv1, m1, o[1][1]);
            FMA2(o[1][2], uv1, m2, o[1][2]);
            FMA2(o[1][3], uv1, m3, o[1][3]);
            FMA2(o[2][0], uv2, m0, o[2][0]);
            FMA2(o[2][1], uv2, m1, o[2][1]);
            FMA2(o[2][2], uv2, m2, o[2][2]);
            FMA2(o[2][3], uv2, m3, o[2][3]);
            FMA2(o[3][0], uv3, m0, o[3][0]);
            FMA2(o[3][1], uv3, m1, o[3][1]);
            FMA2(o[3][2], uv3, m2, o[3][2]);
            FMA2(o[3][3], uv3, m3, o[3][3]);
        }
    }

    // ---- Accumulate directly into output via vector REDG (no partials) ----
    {
        float* obase = out + (size_t)bx * ROWS_T * D_DIM;
        #pragma unroll
        for (int j = 0; j < 4; ++j) {
            float4 lo, hi;
            UNPACK2(lo.x, hi.x, o[j][0]);
            UNPACK2(lo.y, hi.y, o[j][1]);
            UNPACK2(lo.z, hi.z, o[j][2]);
            UNPACK2(lo.w, hi.w, o[j][3]);
            int row = 8 * ty + 2 * j;
            float* p0 = obase + (size_t)row * D_DIM + 4 * tx;
            float* p1 = obase + (size_t)(row + 1) * D_DIM + 4 * tx;
            RED_ADD_V4(p0, lo.x, lo.y, lo.z, lo.w);
            RED_ADD_V4(p1, hi.x, hi.y, hi.z, hi.w);
        }
    }
}

// ---------------------------------------------------------------------------
extern "C" void kernel_launch(void* const* d_in, const int* in_sizes, int n_in,
                              void* d_out, int out_size) {
    const float* x   = nullptr;
    const float* eps = nullptr;
    const float* lam = nullptr;
    const float* eta = nullptr;
    const float* w   = nullptr;
    int ones_seen = 0;
    for (int i = 0; i < n_in; ++i) {
        int sz = in_sizes[i];
        const float* p = (const float*)d_in[i];
        if      (sz == N_ROWS * D_DIM)     x   = p;
        else if (sz == 2 * B_HALF * D_DIM) eps = p;
        else if (sz == D_DIM)              lam = p;
        else if (sz == 4 * B_HALF)         w   = p;
        else if (sz == 1) {
            if (ones_seen == 1) eta = p;   // second size-1 input is eta
            ones_seen++;
        }
    }

    cudaFuncSetAttribute(main_kernel,
                         cudaFuncAttributeMaxDynamicSharedMemorySize, SMEM_BYTES);

    prep_kernel<<<(B_HALF * D_DIM + 255) / 256, 256>>>(eps, lam, eta, w,
                                                       (float4*)d_out);
    main_kernel<<<dim3(N_ROWS / ROWS_T, NG), TBM, SMEM_BYTES>>>(x, (float*)d_out);
}